// round 4
// baseline (speedup 1.0000x reference)
#include <cuda_runtime.h>
#include <cstdint>

#define NN_DIM 5000
#define NF 128
#define NOUT 16
#define NPAD 5120
#define BT 128
#define HW 64            // half-tile width (cols)
#define TPH 68           // half-tile row stride in floats (16B-aligned, conflict-free)
#define NTHREADS 256
#define NMAT_TOTAL 12
#define NHALF (NMAT_TOTAL * 2)

// S1 = feature@W3 (group 0), S2 = feature@W1 (group 1); pad rows stay zero.
__device__ float g_S[2][NPAD][NOUT];

// ---------- packed f32x2 helpers ----------
__device__ __forceinline__ void fma2(unsigned long long &d, unsigned long long a,
                                     unsigned long long b) {
    asm("fma.rn.f32x2 %0, %1, %2, %0;" : "+l"(d) : "l"(a), "l"(b));
}
__device__ __forceinline__ unsigned long long pack2(float x) {
    unsigned long long r;
    asm("mov.b64 %0, {%1, %1};" : "=l"(r) : "f"(x));
    return r;
}
__device__ __forceinline__ float2 unpack2(unsigned long long v) {
    float2 f;
    asm("mov.b64 {%0, %1}, %2;" : "=f"(f.x), "=f"(f.y) : "l"(v));
    return f;
}
__device__ __forceinline__ void red_add_v4(float* p, float x, float y, float z, float w) {
    asm volatile("red.global.add.v4.f32 [%0], {%1, %2, %3, %4};"
                 :: "l"(p), "f"(x), "f"(y), "f"(z), "f"(w) : "memory");
}
// ---------- cp.async helpers ----------
__device__ __forceinline__ void cp_async16(uint32_t dst, const void* src, int sz) {
    asm volatile("cp.async.cg.shared.global [%0], [%1], 16, %2;"
                 :: "r"(dst), "l"(src), "r"(sz));
}
__device__ __forceinline__ void cp_commit() { asm volatile("cp.async.commit_group;"); }
__device__ __forceinline__ void cp_wait0()  { asm volatile("cp.async.wait_group 0;" ::: "memory"); }

// ---------------- prep: S1/S2 = feature @ W, bias-init out ----------------
__global__ void fame_prep(const float* __restrict__ feature,
                          const float* __restrict__ W3, const float* __restrict__ b3,
                          const float* __restrict__ W1, const float* __restrict__ b1,
                          float* __restrict__ out) {
    __shared__ float fsm[NF];
    const int row = blockIdx.x;
    const int t = threadIdx.x;
    fsm[t] = feature[row * NF + t];
    __syncthreads();
    if (t < 32) {
        const int g = t >> 4;
        const int c = t & 15;
        const float* __restrict__ W = g ? W1 : W3;
        float s = 0.f;
#pragma unroll 16
        for (int k = 0; k < NF; k++) s += fsm[k] * W[k * NOUT + c];
        g_S[g][row][c] = s;
    } else if (t < 64) {
        const int c = t - 32;
        out[row * 32 + c] = (c < 16) ? b3[c] : b1[c - 16];
    }
}

__global__ __launch_bounds__(NTHREADS, 2)
void fame_main(const float* __restrict__ A, const float* __restrict__ At,
               const float* __restrict__ wA, const float* __restrict__ wB,
               float* __restrict__ out)
{
    extern __shared__ float smem[];
    // layout: T halves [2][128][68], then S_w bufs [2][ Sj:2048 | Si:2048 ]
    float* Tbuf0 = smem;
    float* Tbuf1 = smem + BT * TPH;
    float* Swb   = smem + 2 * BT * TPH;   // + b*4096: Sj at 0, Si at +2048

    const int t = threadIdx.x;
    const int i0 = blockIdx.y * BT;
    const int j0 = blockIdx.x * BT;

    const int side = t >> 7;
    const int tt = t & 127;
    const int l = tt & 31;
    const int q = tt >> 5;

    // ---- cp.async issue for half-tile p into given buffer ----
    auto issue_half = [&](int p, float* Tb) {
        const int m = p >> 1, h = p & 1;
        const float* __restrict__ M = (m < 3)
            ? A  + (size_t)m       * (size_t)NN_DIM * (size_t)NN_DIM
            : At + (size_t)(m - 3) * (size_t)NN_DIM * (size_t)NN_DIM;
        const uint32_t sbase = (uint32_t)__cvta_generic_to_shared(Tb);
#pragma unroll
        for (int k = 0; k < 8; k++) {
            const int idx = t + NTHREADS * k;        // 0..2047
            const int row = idx >> 4;                // 0..127
            const int c = idx & 15;                  // 16B chunk within 64 cols
            const int gi = i0 + row;
            const int gj = j0 + HW * h + 4 * c;
            int sz = 0;
            if (gi < NN_DIM) {
                int rem = (NN_DIM - gj) * 4;
                sz = rem >= 16 ? 16 : (rem > 0 ? rem : 0);
            }
            const float* src = M + (size_t)(gi < NN_DIM ? gi : 0) * NN_DIM
                                 + (gj < NN_DIM ? gj : 0);
            cp_async16(sbase + (uint32_t)(row * TPH + 4 * c) * 4u, src, sz);
        }
        cp_commit();
    };

    // ---- stage weight-scaled S for matrix m into S_w buffer b ----
    auto stage_sw = [&](int b, int m) {
        const int grp = (m < 3) ? 0 : 1;
        const float w = (m < 3) ? wA[m] : wB[m - 3];
        const float* __restrict__ gs = &g_S[grp][0][0];
        float* __restrict__ Sj = Swb + b * 4096;
        float* __restrict__ Si = Sj + 2048;
        for (int idx = t; idx < 2048; idx += NTHREADS) {
            const int r = idx >> 4, c = idx & 15;
            Sj[idx] = w * gs[(j0 + r) * NOUT + c];
            Si[idx] = w * gs[(i0 + r) * NOUT + c];
        }
    };

    unsigned long long acc[4][8];
#pragma unroll
    for (int a = 0; a < 4; a++)
#pragma unroll
        for (int b = 0; b < 8; b++) acc[a][b] = 0ull;

    auto flush = [&](int goff) {
#pragma unroll
        for (int k = 0; k < 4; k++) {
            const int row = (side == 0) ? (i0 + l + 32 * k)
                                        : (j0 + HW * (k >> 1) + 2 * l + (k & 1));
            if (row < NN_DIM) {
                float* __restrict__ o = out + (size_t)row * 32 + goff;
#pragma unroll
                for (int c = 0; c < 4; c++) {
                    const float2 a = unpack2(acc[k][2 * c]);
                    const float2 b = unpack2(acc[k][2 * c + 1]);
                    red_add_v4(o + 4 * c, a.x, a.y, b.x, b.y);
                }
                acc[k][0] = acc[k][1] = acc[k][2] = acc[k][3] = 0ull;
                acc[k][4] = acc[k][5] = acc[k][6] = acc[k][7] = 0ull;
            }
        }
    };

    // ---- prologue: first half in flight + S_w for matrix 0 ----
    issue_half(0, Tbuf0);
    stage_sw(0, 0);

    for (int p = 0; p < NHALF; p++) {
        const int m = p >> 1, h = p & 1;

        cp_wait0();
        __syncthreads();   // half p resident; all threads done with buf (p+1)&1

        if (p + 1 < NHALF) issue_half(p + 1, (((p + 1) & 1) ? Tbuf1 : Tbuf0));
        if (h == 1 && m + 1 < NMAT_TOTAL) stage_sw((m + 1) & 1, m + 1);

        const float* __restrict__ Tb = (p & 1) ? Tbuf1 : Tbuf0;
        const float* __restrict__ Sjw = Swb + (m & 1) * 4096;
        const float* __restrict__ Siw = Sjw + 2048;

        if (side == 0) {
            // rows l+32k, j in [16q, 16q+16) of this half
            const int jb = 16 * q;
#pragma unroll
            for (int jc = 0; jc < 16; jc += 4) {
                const int j = jb + jc;
                float t0[4], t1[4], t2[4], t3[4];
                *(float4*)t0 = *(const float4*)(Tb + (l +  0) * TPH + j);
                *(float4*)t1 = *(const float4*)(Tb + (l + 32) * TPH + j);
                *(float4*)t2 = *(const float4*)(Tb + (l + 64) * TPH + j);
                *(float4*)t3 = *(const float4*)(Tb + (l + 96) * TPH + j);
#pragma unroll
                for (int jj = 0; jj < 4; jj++) {
                    const ulonglong2* __restrict__ Sp =
                        (const ulonglong2*)(Sjw + (HW * h + j + jj) * NOUT);
                    const ulonglong2 s0 = Sp[0], s1 = Sp[1], s2 = Sp[2], s3 = Sp[3];
                    const unsigned long long m0 = pack2(t0[jj]), m1 = pack2(t1[jj]),
                                             m2 = pack2(t2[jj]), m3 = pack2(t3[jj]);
                    fma2(acc[0][0], m0, s0.x); fma2(acc[0][1], m0, s0.y);
                    fma2(acc[0][2], m0, s1.x); fma2(acc[0][3], m0, s1.y);
                    fma2(acc[0][4], m0, s2.x); fma2(acc[0][5], m0, s2.y);
                    fma2(acc[0][6], m0, s3.x); fma2(acc[0][7], m0, s3.y);
                    fma2(acc[1][0], m1, s0.x); fma2(acc[1][1], m1, s0.y);
                    fma2(acc[1][2], m1, s1.x); fma2(acc[1][3], m1, s1.y);
                    fma2(acc[1][4], m1, s2.x); fma2(acc[1][5], m1, s2.y);
                    fma2(acc[1][6], m1, s3.x); fma2(acc[1][7], m1, s3.y);
                    fma2(acc[2][0], m2, s0.x); fma2(acc[2][1], m2, s0.y);
                    fma2(acc[2][2], m2, s1.x); fma2(acc[2][3], m2, s1.y);
                    fma2(acc[2][4], m2, s2.x); fma2(acc[2][5], m2, s2.y);
                    fma2(acc[2][6], m2, s3.x); fma2(acc[2][7], m2, s3.y);
                    fma2(acc[3][0], m3, s0.x); fma2(acc[3][1], m3, s0.y);
                    fma2(acc[3][2], m3, s1.x); fma2(acc[3][3], m3, s1.y);
                    fma2(acc[3][4], m3, s2.x); fma2(acc[3][5], m3, s2.y);
                    fma2(acc[3][6], m3, s3.x); fma2(acc[3][7], m3, s3.y);
                }
            }
        } else {
            // out rows (2l, 2l+1) of this half; i in [32q, 32q+32)
            const int ko = 2 * h;
            const int ib = 32 * q;
#pragma unroll 4
            for (int i = ib; i < ib + 32; i++) {
                const float2 Tv = *(const float2*)(Tb + i * TPH + 2 * l);
                const ulonglong2* __restrict__ Sp = (const ulonglong2*)(Siw + i * NOUT);
                const ulonglong2 s0 = Sp[0], s1 = Sp[1], s2 = Sp[2], s3 = Sp[3];
                const unsigned long long m0 = pack2(Tv.x), m1 = pack2(Tv.y);
                fma2(acc[ko][0], m0, s0.x); fma2(acc[ko][1], m0, s0.y);
                fma2(acc[ko][2], m0, s1.x); fma2(acc[ko][3], m0, s1.y);
                fma2(acc[ko][4], m0, s2.x); fma2(acc[ko][5], m0, s2.y);
                fma2(acc[ko][6], m0, s3.x); fma2(acc[ko][7], m0, s3.y);
                fma2(acc[ko+1][0], m1, s0.x); fma2(acc[ko+1][1], m1, s0.y);
                fma2(acc[ko+1][2], m1, s1.x); fma2(acc[ko+1][3], m1, s1.y);
                fma2(acc[ko+1][4], m1, s2.x); fma2(acc[ko+1][5], m1, s2.y);
                fma2(acc[ko+1][6], m1, s3.x); fma2(acc[ko+1][7], m1, s3.y);
            }
        }

        if (p == 5) flush(0);   // end of group A (matrices 0..2) -> cols 0..15
    }
    flush(16);                  // group B -> cols 16..31
}

extern "C" void kernel_launch(void* const* d_in, const int* in_sizes, int n_in,
                              void* d_out, int out_size) {
    const float* feature = (const float*)d_in[0];  // [5000,128]
    const float* A       = (const float*)d_in[1];  // [3,5000,5000]
    const float* At      = (const float*)d_in[2];  // [9,5000,5000]
    const float* wb2     = (const float*)d_in[3];  // [3,1]
    const float* wb      = (const float*)d_in[4];  // [9,1]
    const float* W3      = (const float*)d_in[5];  // [128,16]
    const float* b3      = (const float*)d_in[6];  // [16]
    const float* W1      = (const float*)d_in[7];  // [128,16]
    const float* b1      = (const float*)d_in[8];  // [16]
    float* out = (float*)d_out;                    // [5000,32]

    fame_prep<<<NN_DIM, 128>>>(feature, W3, b3, W1, b1, out);

    const int smem_bytes = (2 * BT * TPH + 2 * 4096) * (int)sizeof(float);
    cudaFuncSetAttribute(fame_main, cudaFuncAttributeMaxDynamicSharedMemorySize, smem_bytes);
    dim3 grid((NN_DIM + BT - 1) / BT, (NN_DIM + BT - 1) / BT);
    fame_main<<<grid, NTHREADS, smem_bytes>>>(A, At, wb2, wb, out);
}

// round 5
// speedup vs baseline: 1.1615x; 1.1615x over previous
#include <cuda_runtime.h>
#include <cstdint>

#define NN_DIM 5000
#define NF 128
#define NOUT 16
#define NPAD 5120
#define BT 128
#define TPD 132          // tile row stride (floats): 16B-aligned, conflict-free
#define NTHREADS 512
#define NMAT_TOTAL 12

// S1 = feature@W3 (group 0), S2 = feature@W1 (group 1); pad rows stay zero.
__device__ float g_S[2][NPAD][NOUT];

// ---------- packed f32x2 helpers ----------
__device__ __forceinline__ void fma2(unsigned long long &d, unsigned long long a,
                                     unsigned long long b) {
    asm("fma.rn.f32x2 %0, %1, %2, %0;" : "+l"(d) : "l"(a), "l"(b));
}
__device__ __forceinline__ unsigned long long pack2(float x) {
    unsigned long long r;
    asm("mov.b64 %0, {%1, %1};" : "=l"(r) : "f"(x));
    return r;
}
__device__ __forceinline__ float2 unpack2(unsigned long long v) {
    float2 f;
    asm("mov.b64 {%0, %1}, %2;" : "=f"(f.x), "=f"(f.y) : "l"(v));
    return f;
}
__device__ __forceinline__ void red_add_v4(float* p, float x, float y, float z, float w) {
    asm volatile("red.global.add.v4.f32 [%0], {%1, %2, %3, %4};"
                 :: "l"(p), "f"(x), "f"(y), "f"(z), "f"(w) : "memory");
}
// ---------- cp.async helpers ----------
__device__ __forceinline__ void cp_async16(uint32_t dst, const void* src, int sz) {
    asm volatile("cp.async.cg.shared.global [%0], [%1], 16, %2;"
                 :: "r"(dst), "l"(src), "r"(sz));
}
__device__ __forceinline__ void cp_commit() { asm volatile("cp.async.commit_group;"); }
__device__ __forceinline__ void cp_wait0()  { asm volatile("cp.async.wait_group 0;" ::: "memory"); }

// ---------------- prep: S1/S2 = feature @ W, bias-init out ----------------
__global__ void fame_prep(const float* __restrict__ feature,
                          const float* __restrict__ W3, const float* __restrict__ b3,
                          const float* __restrict__ W1, const float* __restrict__ b1,
                          float* __restrict__ out) {
    __shared__ float fsm[NF];
    const int row = blockIdx.x;
    const int t = threadIdx.x;
    fsm[t] = feature[row * NF + t];
    __syncthreads();
    if (t < 32) {
        const int g = t >> 4;
        const int c = t & 15;
        const float* __restrict__ W = g ? W1 : W3;
        float s = 0.f;
#pragma unroll 16
        for (int k = 0; k < NF; k++) s += fsm[k] * W[k * NOUT + c];
        g_S[g][row][c] = s;
    } else if (t < 64) {
        const int c = t - 32;
        out[row * 32 + c] = (c < 16) ? b3[c] : b1[c - 16];
    }
}

__global__ __launch_bounds__(NTHREADS, 1)
void fame_main(const float* __restrict__ A, const float* __restrict__ At,
               const float* __restrict__ wA, const float* __restrict__ wB,
               float* __restrict__ out)
{
    extern __shared__ float smem[];
    // [2][128*132] T double-buffer, then [2][4096] weight-scaled S (Sj | Si)
    float* Tbuf0 = smem;
    float* Tbuf1 = smem + BT * TPD;
    float* Swb   = smem + 2 * BT * TPD;

    const int t = threadIdx.x;
    const int i0 = blockIdx.y * BT;
    const int j0 = blockIdx.x * BT;

    const int side = t >> 8;       // 0: direct (out rows i), 1: transpose (out rows j)
    const int l = t & 31;
    const int q = (t >> 5) & 7;    // warp index within side (0..7)

    // ---- cp.async issue for full tile of matrix m ----
    auto issue_tile = [&](int m, float* Tb) {
        const float* __restrict__ M = (m < 3)
            ? A  + (size_t)m       * (size_t)NN_DIM * (size_t)NN_DIM
            : At + (size_t)(m - 3) * (size_t)NN_DIM * (size_t)NN_DIM;
        const uint32_t sbase = (uint32_t)__cvta_generic_to_shared(Tb);
#pragma unroll
        for (int k = 0; k < 8; k++) {
            const int idx = t + NTHREADS * k;        // 0..4095
            const int row = idx >> 5;                // 0..127
            const int c = idx & 31;                  // 16B chunk (4 floats)
            const int gi = i0 + row;
            const int gj = j0 + 4 * c;
            int sz = 0;
            if (gi < NN_DIM) {
                const int rem = (NN_DIM - gj) * 4;
                sz = rem >= 16 ? 16 : (rem > 0 ? rem : 0);
            }
            const float* src = M + (size_t)(gi < NN_DIM ? gi : 0) * NN_DIM
                                 + (gj < NN_DIM ? gj : 0);
            cp_async16(sbase + (uint32_t)(row * TPD + 4 * c) * 4u, src, sz);
        }
        cp_commit();
    };

    // ---- stage weight-scaled S for matrix m into S buffer b ----
    auto stage_sw = [&](int b, int m) {
        const int grp = (m < 3) ? 0 : 1;
        const float w = (m < 3) ? wA[m] : wB[m - 3];
        const float* __restrict__ gs = &g_S[grp][0][0];
        float* __restrict__ Sj = Swb + b * 4096;
        float* __restrict__ Si = Sj + 2048;
        for (int idx = t; idx < 2048; idx += NTHREADS) {
            const int r = idx >> 4, c = idx & 15;
            Sj[idx] = w * gs[(j0 + r) * NOUT + c];
            Si[idx] = w * gs[(i0 + r) * NOUT + c];
        }
    };

    unsigned long long acc[4][8];
#pragma unroll
    for (int a = 0; a < 4; a++)
#pragma unroll
        for (int b = 0; b < 8; b++) acc[a][b] = 0ull;

    auto flush = [&](int goff) {
#pragma unroll
        for (int k = 0; k < 4; k++) {
            const int row = (side == 0) ? (i0 + l + 32 * k) : (j0 + 4 * l + k);
            if (row < NN_DIM) {
                float* __restrict__ o = out + (size_t)row * 32 + goff;
#pragma unroll
                for (int c = 0; c < 4; c++) {
                    const float2 a = unpack2(acc[k][2 * c]);
                    const float2 b = unpack2(acc[k][2 * c + 1]);
                    red_add_v4(o + 4 * c, a.x, a.y, b.x, b.y);
                }
            }
            acc[k][0] = acc[k][1] = acc[k][2] = acc[k][3] = 0ull;
            acc[k][4] = acc[k][5] = acc[k][6] = acc[k][7] = 0ull;
        }
    };

    // ---- prologue ----
    issue_tile(0, Tbuf0);
    stage_sw(0, 0);

    for (int m = 0; m < NMAT_TOTAL; m++) {
        cp_wait0();
        __syncthreads();   // tile m resident; everyone done with buffer (m+1)&1

        if (m + 1 < NMAT_TOTAL) {
            issue_tile(m + 1, ((m + 1) & 1) ? Tbuf1 : Tbuf0);
            stage_sw((m + 1) & 1, m + 1);
        }

        const float* __restrict__ Tb  = (m & 1) ? Tbuf1 : Tbuf0;
        const float* __restrict__ Sjw = Swb + (m & 1) * 4096;
        const float* __restrict__ Siw = Sjw + 2048;

        if (side == 0) {
            // out rows i0 + l + 32k; warp q covers j in [16q, 16q+16)
            const int jb = 16 * q;
#pragma unroll
            for (int jc = 0; jc < 16; jc += 4) {
                const int j = jb + jc;
                float t0[4], t1[4], t2[4], t3[4];
                *(float4*)t0 = *(const float4*)(Tb + (l +  0) * TPD + j);
                *(float4*)t1 = *(const float4*)(Tb + (l + 32) * TPD + j);
                *(float4*)t2 = *(const float4*)(Tb + (l + 64) * TPD + j);
                *(float4*)t3 = *(const float4*)(Tb + (l + 96) * TPD + j);
#pragma unroll
                for (int jj = 0; jj < 4; jj++) {
                    const ulonglong2* __restrict__ Sp =
                        (const ulonglong2*)(Sjw + (j + jj) * NOUT);
                    const ulonglong2 s0 = Sp[0], s1 = Sp[1], s2 = Sp[2], s3 = Sp[3];
                    const unsigned long long m0 = pack2(t0[jj]), m1 = pack2(t1[jj]),
                                             m2 = pack2(t2[jj]), m3 = pack2(t3[jj]);
                    fma2(acc[0][0], m0, s0.x); fma2(acc[0][1], m0, s0.y);
                    fma2(acc[0][2], m0, s1.x); fma2(acc[0][3], m0, s1.y);
                    fma2(acc[0][4], m0, s2.x); fma2(acc[0][5], m0, s2.y);
                    fma2(acc[0][6], m0, s3.x); fma2(acc[0][7], m0, s3.y);
                    fma2(acc[1][0], m1, s0.x); fma2(acc[1][1], m1, s0.y);
                    fma2(acc[1][2], m1, s1.x); fma2(acc[1][3], m1, s1.y);
                    fma2(acc[1][4], m1, s2.x); fma2(acc[1][5], m1, s2.y);
                    fma2(acc[1][6], m1, s3.x); fma2(acc[1][7], m1, s3.y);
                    fma2(acc[2][0], m2, s0.x); fma2(acc[2][1], m2, s0.y);
                    fma2(acc[2][2], m2, s1.x); fma2(acc[2][3], m2, s1.y);
                    fma2(acc[2][4], m2, s2.x); fma2(acc[2][5], m2, s2.y);
                    fma2(acc[2][6], m2, s3.x); fma2(acc[2][7], m2, s3.y);
                    fma2(acc[3][0], m3, s0.x); fma2(acc[3][1], m3, s0.y);
                    fma2(acc[3][2], m3, s1.x); fma2(acc[3][3], m3, s1.y);
                    fma2(acc[3][4], m3, s2.x); fma2(acc[3][5], m3, s2.y);
                    fma2(acc[3][6], m3, s3.x); fma2(acc[3][7], m3, s3.y);
                }
            }
        } else {
            // out rows j0 + 4l + k (k=0..3); warp q covers i in [16q, 16q+16)
            const int ib = 16 * q;
#pragma unroll 4
            for (int ii = 0; ii < 16; ii++) {
                const int i = ib + ii;
                const float4 Tv = *(const float4*)(Tb + i * TPD + 4 * l);
                const ulonglong2* __restrict__ Sp = (const ulonglong2*)(Siw + i * NOUT);
                const ulonglong2 s0 = Sp[0], s1 = Sp[1], s2 = Sp[2], s3 = Sp[3];
                const unsigned long long m0 = pack2(Tv.x), m1 = pack2(Tv.y),
                                         m2 = pack2(Tv.z), m3 = pack2(Tv.w);
                fma2(acc[0][0], m0, s0.x); fma2(acc[0][1], m0, s0.y);
                fma2(acc[0][2], m0, s1.x); fma2(acc[0][3], m0, s1.y);
                fma2(acc[0][4], m0, s2.x); fma2(acc[0][5], m0, s2.y);
                fma2(acc[0][6], m0, s3.x); fma2(acc[0][7], m0, s3.y);
                fma2(acc[1][0], m1, s0.x); fma2(acc[1][1], m1, s0.y);
                fma2(acc[1][2], m1, s1.x); fma2(acc[1][3], m1, s1.y);
                fma2(acc[1][4], m1, s2.x); fma2(acc[1][5], m1, s2.y);
                fma2(acc[1][6], m1, s3.x); fma2(acc[1][7], m1, s3.y);
                fma2(acc[2][0], m2, s0.x); fma2(acc[2][1], m2, s0.y);
                fma2(acc[2][2], m2, s1.x); fma2(acc[2][3], m2, s1.y);
                fma2(acc[2][4], m2, s2.x); fma2(acc[2][5], m2, s2.y);
                fma2(acc[2][6], m2, s3.x); fma2(acc[2][7], m2, s3.y);
                fma2(acc[3][0], m3, s0.x); fma2(acc[3][1], m3, s0.y);
                fma2(acc[3][2], m3, s1.x); fma2(acc[3][3], m3, s1.y);
                fma2(acc[3][4], m3, s2.x); fma2(acc[3][5], m3, s2.y);
                fma2(acc[3][6], m3, s3.x); fma2(acc[3][7], m3, s3.y);
            }
        }

        if (m == 2) flush(0);   // group A (matrices 0..2) -> cols 0..15
    }
    flush(16);                  // group B -> cols 16..31
}

extern "C" void kernel_launch(void* const* d_in, const int* in_sizes, int n_in,
                              void* d_out, int out_size) {
    const float* feature = (const float*)d_in[0];  // [5000,128]
    const float* A       = (const float*)d_in[1];  // [3,5000,5000]
    const float* At      = (const float*)d_in[2];  // [9,5000,5000]
    const float* wb2     = (const float*)d_in[3];  // [3,1]
    const float* wb      = (const float*)d_in[4];  // [9,1]
    const float* W3      = (const float*)d_in[5];  // [128,16]
    const float* b3      = (const float*)d_in[6];  // [16]
    const float* W1      = (const float*)d_in[7];  // [128,16]
    const float* b1      = (const float*)d_in[8];  // [16]
    float* out = (float*)d_out;                    // [5000,32]

    fame_prep<<<NN_DIM, 128>>>(feature, W3, b3, W1, b1, out);

    const int smem_bytes = (2 * BT * TPD + 2 * 4096) * (int)sizeof(float);
    cudaFuncSetAttribute(fame_main, cudaFuncAttributeMaxDynamicSharedMemorySize, smem_bytes);
    dim3 grid((NN_DIM + BT - 1) / BT, (NN_DIM + BT - 1) / BT);
    fame_main<<<grid, NTHREADS, smem_bytes>>>(A, At, wb2, wb, out);
}

// round 6
// speedup vs baseline: 1.2974x; 1.1170x over previous
#include <cuda_runtime.h>
#include <cstdint>

#define NN_DIM 5000
#define NF 128
#define NOUT 16
#define NPAD 5120
#define BT 128
#define TPD 132          // tile row stride (floats): 16B-aligned, conflict-free
#define NTHREADS 256
#define NMAT_TOTAL 12

// S1 = feature@W3 (group 0), S2 = feature@W1 (group 1); pad rows stay zero.
__device__ float g_S[2][NPAD][NOUT];

// ---------- packed f32x2 helpers ----------
__device__ __forceinline__ void fma2(unsigned long long &d, unsigned long long a,
                                     unsigned long long b) {
    asm("fma.rn.f32x2 %0, %1, %2, %0;" : "+l"(d) : "l"(a), "l"(b));
}
__device__ __forceinline__ unsigned long long pack2(float x) {
    unsigned long long r;
    asm("mov.b64 %0, {%1, %1};" : "=l"(r) : "f"(x));
    return r;
}
__device__ __forceinline__ float2 unpack2(unsigned long long v) {
    float2 f;
    asm("mov.b64 {%0, %1}, %2;" : "=f"(f.x), "=f"(f.y) : "l"(v));
    return f;
}
__device__ __forceinline__ void red_add_v4(float* p, float x, float y, float z, float w) {
    asm volatile("red.global.add.v4.f32 [%0], {%1, %2, %3, %4};"
                 :: "l"(p), "f"(x), "f"(y), "f"(z), "f"(w) : "memory");
}

// ---------------- prep: S1/S2 = feature @ W, bias-init out ----------------
__global__ void fame_prep(const float* __restrict__ feature,
                          const float* __restrict__ W3, const float* __restrict__ b3,
                          const float* __restrict__ W1, const float* __restrict__ b1,
                          float* __restrict__ out) {
    __shared__ float fsm[NF];
    const int row = blockIdx.x;
    const int t = threadIdx.x;
    fsm[t] = feature[row * NF + t];
    __syncthreads();
    if (t < 32) {
        const int g = t >> 4;
        const int c = t & 15;
        const float* __restrict__ W = g ? W1 : W3;
        float s = 0.f;
#pragma unroll 16
        for (int k = 0; k < NF; k++) s += fsm[k] * W[k * NOUT + c];
        g_S[g][row][c] = s;
    } else if (t < 64) {
        const int c = t - 32;
        out[row * 32 + c] = (c < 16) ? b3[c] : b1[c - 16];
    }
}

__global__ __launch_bounds__(NTHREADS, 2)
void fame_main(const float* __restrict__ A, const float* __restrict__ At,
               const float* __restrict__ wA, const float* __restrict__ wB,
               float* __restrict__ out)
{
    extern __shared__ float smem[];
    float* Tsm = smem;                    // [128][132]
    float* Sjp = smem + BT * TPD;         // 2048 floats: float2 pairs [j2=64][c=16]
    float* Sip = Sjp + 2048;              // 2048 floats: plain [i=128][c=16]

    const int t = threadIdx.x;
    const int wid = t >> 5;
    const int l = t & 31;
    const int i0 = blockIdx.y * BT;
    const int j0 = blockIdx.x * BT;
    const bool fast = (i0 + BT <= NN_DIM) && (j0 + BT <= NN_DIM);

    // ---- stage unscaled S for group g (once per group) ----
    auto stage_S = [&](int g) {
        const float* __restrict__ gs = &g_S[g][0][0];
        float2* __restrict__ SjpV = (float2*)Sjp;
        for (int idx = t; idx < 3072; idx += NTHREADS) {
            if (idx < 1024) {
                const int j2 = idx >> 4, c = idx & 15;
                SjpV[idx] = make_float2(gs[(j0 + 2 * j2) * NOUT + c],
                                        gs[(j0 + 2 * j2 + 1) * NOUT + c]);
            } else {
                const int r = (idx - 1024) >> 4, c = idx & 15;
                Sip[idx - 1024] = gs[(i0 + r) * NOUT + c];
            }
        }
    };

    // acc: 32 x u64 (64 regs). side0: [0..15]=row r0 cols, [16..31]=row r0+32 cols
    //                          side1: 4 rows x 8 c-pairs
    unsigned long long acc[32];
#pragma unroll
    for (int a = 0; a < 32; a++) acc[a] = 0ull;

    // side0 (wid 0..3): rh = wid&1, jr = wid>>1 (64-j range)
    const int rh = wid & 1;
    const int jr = wid >> 1;
    const int r0 = 64 * rh + l;
    // side1 (wid 4..7): ibase = 32*(wid-4); out rows j0 + 4l + k
    const int ibase = 32 * (wid - 4);

    auto flush = [&](int goff) {
        if (wid < 4) {
#pragma unroll
            for (int k = 0; k < 2; k++) {
                const int row = i0 + r0 + 32 * k;
                if (row < NN_DIM) {
                    float* __restrict__ o = out + (size_t)row * 32 + goff;
#pragma unroll
                    for (int c4 = 0; c4 < 4; c4++) {
                        const float2 a0 = unpack2(acc[16 * k + 4 * c4 + 0]);
                        const float2 a1 = unpack2(acc[16 * k + 4 * c4 + 1]);
                        const float2 a2 = unpack2(acc[16 * k + 4 * c4 + 2]);
                        const float2 a3 = unpack2(acc[16 * k + 4 * c4 + 3]);
                        red_add_v4(o + 4 * c4, a0.x + a0.y, a1.x + a1.y,
                                   a2.x + a2.y, a3.x + a3.y);
                    }
                }
            }
        } else {
#pragma unroll
            for (int k = 0; k < 4; k++) {
                const int row = j0 + 4 * l + k;
                if (row < NN_DIM) {
                    float* __restrict__ o = out + (size_t)row * 32 + goff;
#pragma unroll
                    for (int c4 = 0; c4 < 4; c4++) {
                        const float2 a = unpack2(acc[8 * k + 2 * c4]);
                        const float2 b = unpack2(acc[8 * k + 2 * c4 + 1]);
                        red_add_v4(o + 4 * c4, a.x, a.y, b.x, b.y);
                    }
                }
            }
        }
#pragma unroll
        for (int a = 0; a < 32; a++) acc[a] = 0ull;
    };

    for (int m = 0; m < NMAT_TOTAL; m++) {
        const float* __restrict__ M = (m < 3)
            ? A  + (size_t)m       * (size_t)NN_DIM * (size_t)NN_DIM
            : At + (size_t)(m - 3) * (size_t)NN_DIM * (size_t)NN_DIM;
        const float w = (m < 3) ? wA[m] : wB[m - 3];

        __syncthreads();   // previous tile + S fully consumed

        // ---- stage 128x128 tile of M, pre-scaled by w ----
        if (fast) {
#pragma unroll
            for (int k = 0; k < 16; k++) {
                const int idx = t + NTHREADS * k;
                const int row = idx >> 5;
                const int c4 = idx & 31;
                const float4 v = *(const float4*)(M + (size_t)(i0 + row) * NN_DIM + (j0 + 4 * c4));
                float4 s;
                s.x = v.x * w; s.y = v.y * w; s.z = v.z * w; s.w = v.w * w;
                *(float4*)(Tsm + row * TPD + 4 * c4) = s;
            }
        } else {
#pragma unroll
            for (int k = 0; k < 16; k++) {
                const int idx = t + NTHREADS * k;
                const int row = idx >> 5;
                const int c4 = idx & 31;
                const int gi = i0 + row;
                const int gj = j0 + 4 * c4;
                float4 s = make_float4(0.f, 0.f, 0.f, 0.f);
                if (gi < NN_DIM) {
                    const float* __restrict__ p = M + (size_t)gi * NN_DIM + gj;
                    if (gj + 3 < NN_DIM) {
                        const float4 v = *(const float4*)p;
                        s.x = v.x * w; s.y = v.y * w; s.z = v.z * w; s.w = v.w * w;
                    } else {
                        if (gj + 0 < NN_DIM) s.x = p[0] * w;
                        if (gj + 1 < NN_DIM) s.y = p[1] * w;
                        if (gj + 2 < NN_DIM) s.z = p[2] * w;
                    }
                }
                *(float4*)(Tsm + row * TPD + 4 * c4) = s;
            }
        }
        if (m == 0) stage_S(0);
        if (m == 3) stage_S(1);
        __syncthreads();

        if (wid < 4) {
            // ---- side0: rows r0, r0+32; j in [64*jr, 64*jr+64), paired along j ----
            const float* __restrict__ Trow0 = Tsm + r0 * TPD;
            const float* __restrict__ Trow1 = Trow0 + 32 * TPD;
            const unsigned long long* __restrict__ SjpU = (const unsigned long long*)Sjp;
            const int jbase = 64 * jr;
#pragma unroll 4
            for (int jb = 0; jb < 16; jb++) {
                const int j = jbase + 4 * jb;
                const ulonglong2 tv0 = *(const ulonglong2*)(Trow0 + j);  // (T[r0,j],T[r0,j+1]),(j+2,j+3)
                const ulonglong2 tv1 = *(const ulonglong2*)(Trow1 + j);
                const ulonglong2* __restrict__ Sa =
                    (const ulonglong2*)(SjpU + (size_t)(j >> 1) * 16);   // j2 = j/2 row
#pragma unroll
                for (int cc = 0; cc < 8; cc++) {
                    const ulonglong2 sa = Sa[cc];                        // c = 2cc, 2cc+1
                    fma2(acc[2 * cc + 0],  tv0.x, sa.x);
                    fma2(acc[2 * cc + 1],  tv0.x, sa.y);
                    fma2(acc[16 + 2 * cc], tv1.x, sa.x);
                    fma2(acc[17 + 2 * cc], tv1.x, sa.y);
                }
#pragma unroll
                for (int cc = 0; cc < 8; cc++) {
                    const ulonglong2 sb = Sa[8 + cc];                    // j2+1 row
                    fma2(acc[2 * cc + 0],  tv0.y, sb.x);
                    fma2(acc[2 * cc + 1],  tv0.y, sb.y);
                    fma2(acc[16 + 2 * cc], tv1.y, sb.x);
                    fma2(acc[17 + 2 * cc], tv1.y, sb.y);
                }
            }
        } else {
            // ---- side1: out rows j0+4l+k; i in [ibase, ibase+32) ----
#pragma unroll 4
            for (int ii = 0; ii < 32; ii++) {
                const int i = ibase + ii;
                const float4 Tv = *(const float4*)(Tsm + i * TPD + 4 * l);
                const ulonglong2* __restrict__ Sp = (const ulonglong2*)(Sip + i * NOUT);
                const ulonglong2 s0 = Sp[0], s1 = Sp[1], s2 = Sp[2], s3 = Sp[3];
                const unsigned long long m0 = pack2(Tv.x), m1 = pack2(Tv.y),
                                         m2 = pack2(Tv.z), m3 = pack2(Tv.w);
                fma2(acc[0], m0, s0.x); fma2(acc[1], m0, s0.y);
                fma2(acc[2], m0, s1.x); fma2(acc[3], m0, s1.y);
                fma2(acc[4], m0, s2.x); fma2(acc[5], m0, s2.y);
                fma2(acc[6], m0, s3.x); fma2(acc[7], m0, s3.y);
                fma2(acc[8],  m1, s0.x); fma2(acc[9],  m1, s0.y);
                fma2(acc[10], m1, s1.x); fma2(acc[11], m1, s1.y);
                fma2(acc[12], m1, s2.x); fma2(acc[13], m1, s2.y);
                fma2(acc[14], m1, s3.x); fma2(acc[15], m1, s3.y);
                fma2(acc[16], m2, s0.x); fma2(acc[17], m2, s0.y);
                fma2(acc[18], m2, s1.x); fma2(acc[19], m2, s1.y);
                fma2(acc[20], m2, s2.x); fma2(acc[21], m2, s2.y);
                fma2(acc[22], m2, s3.x); fma2(acc[23], m2, s3.y);
                fma2(acc[24], m3, s0.x); fma2(acc[25], m3, s0.y);
                fma2(acc[26], m3, s1.x); fma2(acc[27], m3, s1.y);
                fma2(acc[28], m3, s2.x); fma2(acc[29], m3, s2.y);
                fma2(acc[30], m3, s3.x); fma2(acc[31], m3, s3.y);
            }
        }

        if (m == 2) flush(0);   // group A (matrices 0..2) -> cols 0..15
    }
    flush(16);                  // group B -> cols 16..31
}

extern "C" void kernel_launch(void* const* d_in, const int* in_sizes, int n_in,
                              void* d_out, int out_size) {
    const float* feature = (const float*)d_in[0];  // [5000,128]
    const float* A       = (const float*)d_in[1];  // [3,5000,5000]
    const float* At      = (const float*)d_in[2];  // [9,5000,5000]
    const float* wb2     = (const float*)d_in[3];  // [3,1]
    const float* wb      = (const float*)d_in[4];  // [9,1]
    const float* W3      = (const float*)d_in[5];  // [128,16]
    const float* b3      = (const float*)d_in[6];  // [16]
    const float* W1      = (const float*)d_in[7];  // [128,16]
    const float* b1      = (const float*)d_in[8];  // [16]
    float* out = (float*)d_out;                    // [5000,32]

    fame_prep<<<NN_DIM, 128>>>(feature, W3, b3, W1, b1, out);

    const int smem_bytes = (BT * TPD + 2 * 2048) * (int)sizeof(float);
    cudaFuncSetAttribute(fame_main, cudaFuncAttributeMaxDynamicSharedMemorySize, smem_bytes);
    dim3 grid((NN_DIM + BT - 1) / BT, (NN_DIM + BT - 1) / BT);
    fame_main<<<grid, NTHREADS, smem_bytes>>>(A, At, wb2, wb, out);
}

// round 8
// speedup vs baseline: 1.8702x; 1.4415x over previous
#include <cuda_runtime.h>
#include <cstdint>

#define NN 5000
#define BT 128
#define TPD 132
#define NPAD 5120
#define NTHREADS 256
#define NMAT_TOTAL 12

// S1t/S2t row stride (floats); (4n + k) mod 32 banks -> conflict-free frags
#define SPD 132

__device__ float g_St[2][16][NPAD];   // transposed supports; pad rows zero

// ---------------- helpers ----------------
__device__ __forceinline__ uint32_t f2tf32(float x) {
    uint32_t r;
    asm("cvt.rna.tf32.f32 %0, %1;" : "=r"(r) : "f"(x));
    return r;
}
__device__ __forceinline__ void mma_tf32(float* d, uint32_t a0, uint32_t a1,
                                         uint32_t a2, uint32_t a3,
                                         uint32_t b0, uint32_t b1) {
    asm volatile(
        "mma.sync.aligned.m16n8k8.row.col.f32.tf32.tf32.f32 "
        "{%0,%1,%2,%3}, {%4,%5,%6,%7}, {%8,%9}, {%0,%1,%2,%3};"
        : "+f"(d[0]), "+f"(d[1]), "+f"(d[2]), "+f"(d[3])
        : "r"(a0), "r"(a1), "r"(a2), "r"(a3), "r"(b0), "r"(b1));
}
__device__ __forceinline__ void red_add_v2(float* p, float x, float y) {
    asm volatile("red.global.add.v2.f32 [%0], {%1, %2};"
                 :: "l"(p), "f"(x), "f"(y) : "memory");
}

// ---------------- prep: g_St = (feature @ W)^T, bias-init out ----------------
__global__ void fame_prep(const float* __restrict__ feature,
                          const float* __restrict__ W3, const float* __restrict__ b3,
                          const float* __restrict__ W1, const float* __restrict__ b1,
                          float* __restrict__ out) {
    __shared__ float fsm[128];
    const int row = blockIdx.x;
    const int t = threadIdx.x;
    fsm[t] = feature[row * 128 + t];
    __syncthreads();
    if (t < 32) {
        const int g = t >> 4;
        const int c = t & 15;
        const float* __restrict__ W = g ? W1 : W3;
        float s = 0.f;
#pragma unroll 16
        for (int k = 0; k < 128; k++) s += fsm[k] * W[k * 16 + c];
        g_St[g][c][row] = s;
    } else if (t < 64) {
        const int c = t - 32;
        out[row * 32 + c] = (c < 16) ? b3[c] : b1[c - 16];
    }
}

// ---------------- main: TF32 mma.sync fused merged-GCN ----------------
__global__ __launch_bounds__(NTHREADS, 2)
void fame_main(const float* __restrict__ A, const float* __restrict__ At,
               const float* __restrict__ wA, const float* __restrict__ wB,
               float* __restrict__ out)
{
    extern __shared__ float smem[];
    float* Tsm = smem;                 // [128][132], tf32-rounded, w-scaled
    float* S1t = smem + BT * TPD;      // [16][132]  support^T rows j0..
    float* S2t = S1t + 16 * SPD;       // [16][132]  support^T rows i0..

    const int t = threadIdx.x;
    const int wid = t >> 5, lane = t & 31;
    const int p = lane >> 2, q = lane & 3;
    const int side = wid >> 2;         // 0: direct GEMM, 1: transpose GEMM
    const int rbase = 32 * (wid & 3);
    const int i0 = blockIdx.y * BT, j0 = blockIdx.x * BT;
    const bool interior = (i0 + BT <= NN) && (j0 + BT <= NN);

    float acc[16];
#pragma unroll
    for (int a = 0; a < 16; a++) acc[a] = 0.f;

    for (int m = 0; m < NMAT_TOTAL; m++) {
        const float* __restrict__ M = (m < 3)
            ? A  + (size_t)m       * (size_t)NN * (size_t)NN
            : At + (size_t)(m - 3) * (size_t)NN * (size_t)NN;
        const int g = (m < 3) ? 0 : 1;
        const float w = (m < 3) ? wA[m] : wB[m - 3];

        __syncthreads();   // previous tile fully consumed

        // ---- stage T tile: scale by w, round to tf32 ----
        if (interior) {
#pragma unroll
            for (int k = 0; k < 16; k++) {
                const int idx = t + NTHREADS * k;
                const int row = idx >> 5, c4 = idx & 31;
                const float4 v = *(const float4*)(M + (size_t)(i0 + row) * NN + (j0 + 4 * c4));
                uint4 s;
                s.x = f2tf32(v.x * w); s.y = f2tf32(v.y * w);
                s.z = f2tf32(v.z * w); s.w = f2tf32(v.w * w);
                *(uint4*)(Tsm + row * TPD + 4 * c4) = s;
            }
        } else {
#pragma unroll
            for (int k = 0; k < 16; k++) {
                const int idx = t + NTHREADS * k;
                const int row = idx >> 5, c4 = idx & 31;
                const int gi = i0 + row, gj = j0 + 4 * c4;
                float4 v = make_float4(0.f, 0.f, 0.f, 0.f);
                if (gi < NN) {
                    const float* __restrict__ pp = M + (size_t)gi * NN + gj;
                    if (gj + 3 < NN) v = *(const float4*)pp;
                    else {
                        if (gj + 0 < NN) v.x = pp[0];
                        if (gj + 1 < NN) v.y = pp[1];
                        if (gj + 2 < NN) v.z = pp[2];
                    }
                }
                uint4 s;
                s.x = f2tf32(v.x * w); s.y = f2tf32(v.y * w);
                s.z = f2tf32(v.z * w); s.w = f2tf32(v.w * w);
                *(uint4*)(Tsm + row * TPD + 4 * c4) = s;
            }
        }
        // ---- stage S^T tiles once per group (unscaled; w lives in T) ----
        if (m == 0 || m == 3) {
            for (int idx = t; idx < 4096; idx += NTHREADS) {
                const int half = idx >> 11;
                const int n = (idx >> 7) & 15, k = idx & 127;
                const float v = g_St[g][n][(half ? i0 : j0) + k];
                float* __restrict__ dst = half ? S2t : S1t;
                dst[n * SPD + k] = __uint_as_float(f2tf32(v));
            }
        }
        __syncthreads();

        // ---- warp-level TF32 mma over K=128 ----
        if (side == 0) {
            const float* __restrict__ Ta = Tsm + (rbase + p) * TPD + q;
            const float* __restrict__ Bp = S1t + p * SPD + q;
#pragma unroll 4
            for (int ks = 0; ks < 16; ks++) {
                const int kb = 8 * ks;
                const uint32_t a0 = __float_as_uint(Ta[kb]);
                const uint32_t a1 = __float_as_uint(Ta[8 * TPD + kb]);
                const uint32_t a2 = __float_as_uint(Ta[kb + 4]);
                const uint32_t a3 = __float_as_uint(Ta[8 * TPD + kb + 4]);
                const uint32_t a4 = __float_as_uint(Ta[16 * TPD + kb]);
                const uint32_t a5 = __float_as_uint(Ta[24 * TPD + kb]);
                const uint32_t a6 = __float_as_uint(Ta[16 * TPD + kb + 4]);
                const uint32_t a7 = __float_as_uint(Ta[24 * TPD + kb + 4]);
                const uint32_t b0 = __float_as_uint(Bp[kb]);
                const uint32_t b1 = __float_as_uint(Bp[kb + 4]);
                const uint32_t b2 = __float_as_uint(Bp[8 * SPD + kb]);
                const uint32_t b3 = __float_as_uint(Bp[8 * SPD + kb + 4]);
                mma_tf32(acc + 0,  a0, a1, a2, a3, b0, b1);
                mma_tf32(acc + 4,  a0, a1, a2, a3, b2, b3);
                mma_tf32(acc + 8,  a4, a5, a6, a7, b0, b1);
                mma_tf32(acc + 12, a4, a5, a6, a7, b2, b3);
            }
        } else {
            const float* __restrict__ Tb = Tsm + rbase + p;   // read transposed
            const float* __restrict__ Bp = S2t + p * SPD + q;
#pragma unroll 4
            for (int ks = 0; ks < 16; ks++) {
                const int kb = 8 * ks;
                const float* __restrict__ Tc = Tb + (kb + q) * TPD;
                const uint32_t a0 = __float_as_uint(Tc[0]);
                const uint32_t a1 = __float_as_uint(Tc[8]);
                const uint32_t a2 = __float_as_uint(Tc[4 * TPD]);
                const uint32_t a3 = __float_as_uint(Tc[4 * TPD + 8]);
                const uint32_t a4 = __float_as_uint(Tc[16]);
                const uint32_t a5 = __float_as_uint(Tc[24]);
                const uint32_t a6 = __float_as_uint(Tc[4 * TPD + 16]);
                const uint32_t a7 = __float_as_uint(Tc[4 * TPD + 24]);
                const uint32_t b0 = __float_as_uint(Bp[kb]);
                const uint32_t b1 = __float_as_uint(Bp[kb + 4]);
                const uint32_t b2 = __float_as_uint(Bp[8 * SPD + kb]);
                const uint32_t b3 = __float_as_uint(Bp[8 * SPD + kb + 4]);
                mma_tf32(acc + 0,  a0, a1, a2, a3, b0, b1);
                mma_tf32(acc + 4,  a0, a1, a2, a3, b2, b3);
                mma_tf32(acc + 8,  a4, a5, a6, a7, b0, b1);
                mma_tf32(acc + 12, a4, a5, a6, a7, b2, b3);
            }
        }

        // ---- flush per group ----
        if (m == 2 || m == NMAT_TOTAL - 1) {
            const int goff = (m == 2) ? 0 : 16;
            const int base_row = ((side == 0) ? i0 : j0) + rbase;
#pragma unroll
            for (int rg = 0; rg < 2; rg++)
#pragma unroll
                for (int ng = 0; ng < 2; ng++) {
                    float* ap = acc + rg * 8 + ng * 4;
                    const int r0 = base_row + 16 * rg + p;
                    const int col = goff + 8 * ng + 2 * q;
                    if (r0 < NN)     red_add_v2(out + (size_t)r0 * 32 + col, ap[0], ap[1]);
                    if (r0 + 8 < NN) red_add_v2(out + (size_t)(r0 + 8) * 32 + col, ap[2], ap[3]);
                }
#pragma unroll
            for (int a = 0; a < 16; a++) acc[a] = 0.f;
        }
    }
}

extern "C" void kernel_launch(void* const* d_in, const int* in_sizes, int n_in,
                              void* d_out, int out_size) {
    const float* feature = (const float*)d_in[0];  // [5000,128]
    const float* A       = (const float*)d_in[1];  // [3,5000,5000]
    const float* At      = (const float*)d_in[2];  // [9,5000,5000]
    const float* wb2     = (const float*)d_in[3];  // [3,1]
    const float* wb      = (const float*)d_in[4];  // [9,1]
    const float* W3      = (const float*)d_in[5];  // [128,16]
    const float* b3      = (const float*)d_in[6];  // [16]
    const float* W1      = (const float*)d_in[7];  // [128,16]
    const float* b1      = (const float*)d_in[8];  // [16]
    float* out = (float*)d_out;                    // [5000,32]

    fame_prep<<<NN, 128>>>(feature, W3, b3, W1, b1, out);

    const int smem_bytes = (BT * TPD + 2 * 16 * SPD) * (int)sizeof(float);
    cudaFuncSetAttribute(fame_main, cudaFuncAttributeMaxDynamicSharedMemorySize, smem_bytes);
    dim3 grid((NN + BT - 1) / BT, (NN + BT - 1) / BT);
    fame_main<<<grid, NTHREADS, smem_bytes>>>(A, At, wb2, wb, out);
}

// round 9
// speedup vs baseline: 2.0195x; 1.0798x over previous
#include <cuda_runtime.h>
#include <cstdint>

#define NN 5000
#define BT 128
#define TPD 132          // T row stride (floats), conflict-free
#define SPD 132          // S row stride
#define NPAD 5120
#define NTHREADS 512
#define NMAT 12

__device__ float g_St[2][16][NPAD];   // transposed supports; pad rows zero

// ---------------- helpers ----------------
__device__ __forceinline__ uint32_t f2tf32(float x) {
    uint32_t r;
    asm("cvt.rna.tf32.f32 %0, %1;" : "=r"(r) : "f"(x));
    return r;
}
__device__ __forceinline__ void mma_tf32(float* d, uint32_t a0, uint32_t a1,
                                         uint32_t a2, uint32_t a3,
                                         uint32_t b0, uint32_t b1) {
    asm volatile(
        "mma.sync.aligned.m16n8k8.row.col.f32.tf32.tf32.f32 "
        "{%0,%1,%2,%3}, {%4,%5,%6,%7}, {%8,%9}, {%0,%1,%2,%3};"
        : "+f"(d[0]), "+f"(d[1]), "+f"(d[2]), "+f"(d[3])
        : "r"(a0), "r"(a1), "r"(a2), "r"(a3), "r"(b0), "r"(b1));
}
__device__ __forceinline__ void red_add_v2(float* p, float x, float y) {
    asm volatile("red.global.add.v2.f32 [%0], {%1, %2};"
                 :: "l"(p), "f"(x), "f"(y) : "memory");
}
__device__ __forceinline__ void cp_async16(uint32_t dst, const void* src, int sz) {
    asm volatile("cp.async.cg.shared.global [%0], [%1], 16, %2;"
                 :: "r"(dst), "l"(src), "r"(sz));
}
__device__ __forceinline__ void cp_commit() { asm volatile("cp.async.commit_group;"); }
template <int N>
__device__ __forceinline__ void cp_wait() {
    asm volatile("cp.async.wait_group %0;" :: "n"(N) : "memory");
}

// ---------------- prep: g_St = (feature @ W)^T, bias-init out ----------------
__global__ void fame_prep(const float* __restrict__ feature,
                          const float* __restrict__ W3, const float* __restrict__ b3,
                          const float* __restrict__ W1, const float* __restrict__ b1,
                          float* __restrict__ out) {
    __shared__ float fsm[128];
    const int row = blockIdx.x;
    const int t = threadIdx.x;
    fsm[t] = feature[row * 128 + t];
    __syncthreads();
    if (t < 32) {
        const int g = t >> 4;
        const int c = t & 15;
        const float* __restrict__ W = g ? W1 : W3;
        float s = 0.f;
#pragma unroll 16
        for (int k = 0; k < 128; k++) s += fsm[k] * W[k * 16 + c];
        g_St[g][c][row] = s;
    } else if (t < 64) {
        const int c = t - 32;
        out[row * 32 + c] = (c < 16) ? b3[c] : b1[c - 16];
    }
}

// ---------------- main: cp.async-pipelined TF32 mma fused merged-GCN ----------------
__global__ __launch_bounds__(NTHREADS, 1)
void fame_main(const float* __restrict__ A, const float* __restrict__ At,
               const float* __restrict__ wA, const float* __restrict__ wB,
               float* __restrict__ out)
{
    extern __shared__ float smem[];
    float* T0   = smem;                      // [128][132] raw f32 tile, buf 0
    float* T1   = smem + BT * TPD;           // buf 1
    float* Sbuf = smem + 2 * BT * TPD;       // [parity][ S1w: 16x132 | S2w: 16x132 ]

    const int t = threadIdx.x;
    const int wid = t >> 5, lane = t & 31;
    const int p = lane >> 2, q = lane & 3;
    const int side = wid >> 3;               // 0: direct GEMM, 1: transpose GEMM
    const int wsub = wid & 7;                // 16-row slice within side
    const int i0 = blockIdx.y * BT, j0 = blockIdx.x * BT;

    // ---- cp.async issue for tile of matrix m (raw copy; zero-fill at edges) ----
    auto issue_tile = [&](int m, float* Tb) {
        const float* __restrict__ M = (m < 3)
            ? A  + (size_t)m       * (size_t)NN * (size_t)NN
            : At + (size_t)(m - 3) * (size_t)NN * (size_t)NN;
        const uint32_t sbase = (uint32_t)__cvta_generic_to_shared(Tb);
#pragma unroll
        for (int k = 0; k < 8; k++) {
            const int idx = t + NTHREADS * k;     // 0..4095
            const int row = idx >> 5;             // 0..127
            const int c4 = idx & 31;              // 16B chunk
            const int gi = i0 + row;
            const int gj = j0 + 4 * c4;
            int sz = 0;
            if (gi < NN) {
                const int rem = (NN - gj) * 4;
                sz = rem >= 16 ? 16 : (rem > 0 ? rem : 0);
            }
            const float* src = M + (size_t)(gi < NN ? gi : 0) * NN
                                 + (gj < NN ? gj : 0);
            cp_async16(sbase + (uint32_t)(row * TPD + 4 * c4) * 4u, src, sz);
        }
        cp_commit();
    };

    // ---- stage weight-scaled tf32 S^T tiles for matrix m (parity m&1) ----
    auto stage_S = [&](int m) {
        const int g = (m < 3) ? 0 : 1;
        const float w = (m < 3) ? wA[m] : wB[m - 3];
        float* __restrict__ S1w = Sbuf + (m & 1) * (2 * 16 * SPD);
        float* __restrict__ S2w = S1w + 16 * SPD;
#pragma unroll
        for (int it = 0; it < 8; it++) {
            const int idx = t + NTHREADS * it;    // 0..4095
            const int half = idx >> 11;
            const int n = (idx >> 7) & 15, k = idx & 127;
            const float v = w * g_St[g][n][(half ? i0 : j0) + k];
            (half ? S2w : S1w)[n * SPD + k] = __uint_as_float(f2tf32(v));
        }
    };

    float acc[8];
#pragma unroll
    for (int a = 0; a < 8; a++) acc[a] = 0.f;

    auto flush = [&](int goff) {
        const int base_row = ((side == 0) ? i0 : j0) + 16 * wsub;
#pragma unroll
        for (int ng = 0; ng < 2; ng++) {
            float* ap = acc + 4 * ng;
            const int col = goff + 8 * ng + 2 * q;
            const int r0 = base_row + p;
            if (r0 < NN)     red_add_v2(out + (size_t)r0 * 32 + col, ap[0], ap[1]);
            if (r0 + 8 < NN) red_add_v2(out + (size_t)(r0 + 8) * 32 + col, ap[2], ap[3]);
        }
#pragma unroll
        for (int a = 0; a < 8; a++) acc[a] = 0.f;
    };

    // ---- prologue ----
    issue_tile(0, T0);

    for (int m = 0; m < NMAT; m++) {
        __syncthreads();   // all warps done with buf (m+1)&1 and S parity m&1

        if (m + 1 < NMAT) {
            issue_tile(m + 1, ((m + 1) & 1) ? T1 : T0);
            stage_S(m);
            cp_wait<1>();  // tile m resident (one tile still in flight)
        } else {
            stage_S(m);
            cp_wait<0>();
        }
        __syncthreads();   // S staged + tile m visible to all

        const float* __restrict__ Tb  = (m & 1) ? T1 : T0;
        const float* __restrict__ S1w = Sbuf + (m & 1) * (2 * 16 * SPD);
        const float* __restrict__ S2w = S1w + 16 * SPD;

        if (side == 0) {
            const float* __restrict__ Ta = Tb + (16 * wsub + p) * TPD + q;
            const float* __restrict__ Bp = S1w + p * SPD + q;
#pragma unroll 4
            for (int ks = 0; ks < 16; ks++) {
                const int kb = 8 * ks;
                const uint32_t a0 = f2tf32(Ta[kb]);
                const uint32_t a1 = f2tf32(Ta[8 * TPD + kb]);
                const uint32_t a2 = f2tf32(Ta[kb + 4]);
                const uint32_t a3 = f2tf32(Ta[8 * TPD + kb + 4]);
                const uint32_t b0 = __float_as_uint(Bp[kb]);
                const uint32_t b1 = __float_as_uint(Bp[kb + 4]);
                const uint32_t b2 = __float_as_uint(Bp[8 * SPD + kb]);
                const uint32_t b3 = __float_as_uint(Bp[8 * SPD + kb + 4]);
                mma_tf32(acc,     a0, a1, a2, a3, b0, b1);
                mma_tf32(acc + 4, a0, a1, a2, a3, b2, b3);
            }
        } else {
            const int jb = 16 * wsub;
            const float* __restrict__ Bp = S2w + p * SPD + q;
#pragma unroll 4
            for (int ks = 0; ks < 16; ks++) {
                const int kb = 8 * ks;
                const float* __restrict__ Tc = Tb + (kb + q) * TPD + jb + p;
                const uint32_t a0 = f2tf32(Tc[0]);
                const uint32_t a1 = f2tf32(Tc[8]);
                const uint32_t a2 = f2tf32(Tc[4 * TPD]);
                const uint32_t a3 = f2tf32(Tc[4 * TPD + 8]);
                const uint32_t b0 = __float_as_uint(Bp[kb]);
                const uint32_t b1 = __float_as_uint(Bp[kb + 4]);
                const uint32_t b2 = __float_as_uint(Bp[8 * SPD + kb]);
                const uint32_t b3 = __float_as_uint(Bp[8 * SPD + kb + 4]);
                mma_tf32(acc,     a0, a1, a2, a3, b0, b1);
                mma_tf32(acc + 4, a0, a1, a2, a3, b2, b3);
            }
        }

        if (m == 2) flush(0);          // group A -> cols 0..15
        if (m == NMAT - 1) flush(16);  // group B -> cols 16..31
    }
}

extern "C" void kernel_launch(void* const* d_in, const int* in_sizes, int n_in,
                              void* d_out, int out_size) {
    const float* feature = (const float*)d_in[0];  // [5000,128]
    const float* A       = (const float*)d_in[1];  // [3,5000,5000]
    const float* At      = (const float*)d_in[2];  // [9,5000,5000]
    const float* wb2     = (const float*)d_in[3];  // [3,1]
    const float* wb      = (const float*)d_in[4];  // [9,1]
    const float* W3      = (const float*)d_in[5];  // [128,16]
    const float* b3      = (const float*)d_in[6];  // [16]
    const float* W1      = (const float*)d_in[7];  // [128,16]
    const float* b1      = (const float*)d_in[8];  // [16]
    float* out = (float*)d_out;                    // [5000,32]

    fame_prep<<<NN, 128>>>(feature, W3, b3, W1, b1, out);

    const int smem_bytes = (2 * BT * TPD + 2 * 2 * 16 * SPD) * (int)sizeof(float);
    cudaFuncSetAttribute(fame_main, cudaFuncAttributeMaxDynamicSharedMemorySize, smem_bytes);
    dim3 grid((NN + BT - 1) / BT, (NN + BT - 1) / BT);
    fame_main<<<grid, NTHREADS, smem_bytes>>>(A, At, wb2, wb, out);
}

// round 10
// speedup vs baseline: 2.5981x; 1.2865x over previous
#include <cuda_runtime.h>
#include <cstdint>

#define NN 5000
#define BT 128
#define TPD 132          // T row stride (floats), 16B-aligned, conflict-free
#define SPD 132          // S row stride
#define NPAD 5120
#define NTHREADS 512
#define NMAT 12

__device__ float g_St[2][16][NPAD];   // transposed supports; pad rows zero

// ---------------- helpers ----------------
__device__ __forceinline__ uint32_t f2tf32(float x) {
    uint32_t r;
    asm("cvt.rna.tf32.f32 %0, %1;" : "=r"(r) : "f"(x));
    return r;
}
__device__ __forceinline__ void mma_tf32(float* d, uint32_t a0, uint32_t a1,
                                         uint32_t a2, uint32_t a3,
                                         uint32_t b0, uint32_t b1) {
    asm volatile(
        "mma.sync.aligned.m16n8k8.row.col.f32.tf32.tf32.f32 "
        "{%0,%1,%2,%3}, {%4,%5,%6,%7}, {%8,%9}, {%0,%1,%2,%3};"
        : "+f"(d[0]), "+f"(d[1]), "+f"(d[2]), "+f"(d[3])
        : "r"(a0), "r"(a1), "r"(a2), "r"(a3), "r"(b0), "r"(b1));
}
__device__ __forceinline__ void red_add_v2(float* p, float x, float y) {
    asm volatile("red.global.add.v2.f32 [%0], {%1, %2};"
                 :: "l"(p), "f"(x), "f"(y) : "memory");
}
__device__ __forceinline__ void cp_async16(uint32_t dst, const void* src, int sz) {
    asm volatile("cp.async.cg.shared.global [%0], [%1], 16, %2;"
                 :: "r"(dst), "l"(src), "r"(sz));
}
__device__ __forceinline__ void cp_commit() { asm volatile("cp.async.commit_group;"); }
template <int N>
__device__ __forceinline__ void cp_wait() {
    asm volatile("cp.async.wait_group %0;" :: "n"(N) : "memory");
}

// ---------------- prep: g_St = (feature @ W)^T, bias-init out ----------------
__global__ void fame_prep(const float* __restrict__ feature,
                          const float* __restrict__ W3, const float* __restrict__ b3,
                          const float* __restrict__ W1, const float* __restrict__ b1,
                          float* __restrict__ out) {
    __shared__ float fsm[128];
    const int row = blockIdx.x;
    const int t = threadIdx.x;
    fsm[t] = feature[row * 128 + t];
    __syncthreads();
    if (t < 32) {
        const int g = t >> 4;
        const int c = t & 15;
        const float* __restrict__ W = g ? W1 : W3;
        float s = 0.f;
#pragma unroll 16
        for (int k = 0; k < 128; k++) s += fsm[k] * W[k * 16 + c];
        g_St[g][c][row] = s;
    } else if (t < 64) {
        const int c = t - 32;
        out[row * 32 + c] = (c < 16) ? b3[c] : b1[c - 16];
    }
}

// ---------------- main: 3-stage cp.async ring, reg-resident B, TF32 mma ----------------
__global__ __launch_bounds__(NTHREADS, 1)
void fame_main(const float* __restrict__ A, const float* __restrict__ At,
               const float* __restrict__ wA, const float* __restrict__ wB,
               float* __restrict__ out)
{
    extern __shared__ float smem[];
    float* S1u = smem + 3 * BT * TPD;        // [16][132] tf32 S^T rows j0.. (unscaled)
    float* S2u = S1u + 16 * SPD;             // [16][132] tf32 S^T rows i0..

    const int t = threadIdx.x;
    const int wid = t >> 5, lane = t & 31;
    const int p = lane >> 2, q = lane & 3;
    const int side = wid >> 3;               // 0: direct GEMM, 1: transpose GEMM
    const int wsub = wid & 7;                // 16-row slice within side
    const int i0 = blockIdx.y * BT, j0 = blockIdx.x * BT;

    // ---- cp.async raw-copy of tile m into ring slot ----
    auto issue_tile = [&](int m) {
        const float* __restrict__ M = (m < 3)
            ? A  + (size_t)m       * (size_t)NN * (size_t)NN
            : At + (size_t)(m - 3) * (size_t)NN * (size_t)NN;
        const int slot = m - (m / 3) * 3;
        const uint32_t sbase =
            (uint32_t)__cvta_generic_to_shared(smem + slot * BT * TPD);
#pragma unroll
        for (int k = 0; k < 8; k++) {
            const int idx = t + NTHREADS * k;     // 0..4095
            const int row = idx >> 5;
            const int c4 = idx & 31;
            const int gi = i0 + row;
            const int gj = j0 + 4 * c4;
            int sz = 0;
            if (gi < NN) {
                const int rem = (NN - gj) * 4;
                sz = rem >= 16 ? 16 : (rem > 0 ? rem : 0);
            }
            const float* src = M + (size_t)(gi < NN ? gi : 0) * NN
                                 + (gj < NN ? gj : 0);
            cp_async16(sbase + (uint32_t)(row * TPD + 4 * c4) * 4u, src, sz);
        }
        cp_commit();
    };

    // ---- stage unscaled tf32 S^T tiles for group g ----
    auto stage_S = [&](int g) {
#pragma unroll
        for (int it = 0; it < 8; it++) {
            const int idx = t + NTHREADS * it;    // 0..4095
            const int half = idx >> 11;
            const int n = (idx >> 7) & 15, k = idx & 127;
            const float v = g_St[g][n][(half ? i0 : j0) + k];
            (half ? S2u : S1u)[n * SPD + k] = __uint_as_float(f2tf32(v));
        }
    };

    uint32_t breg[64];
    auto load_B = [&]() {
        const float* __restrict__ Bp = (side ? S2u : S1u) + p * SPD + q;
#pragma unroll
        for (int ks = 0; ks < 16; ks++) {
            const int kb = 8 * ks;
            breg[4 * ks + 0] = __float_as_uint(Bp[kb]);
            breg[4 * ks + 1] = __float_as_uint(Bp[kb + 4]);
            breg[4 * ks + 2] = __float_as_uint(Bp[8 * SPD + kb]);
            breg[4 * ks + 3] = __float_as_uint(Bp[8 * SPD + kb + 4]);
        }
    };

    float acc[8], araw[8];
#pragma unroll
    for (int a = 0; a < 8; a++) { acc[a] = 0.f; araw[a] = 0.f; }

    auto flush = [&](int goff) {
        const int base_row = ((side == 0) ? i0 : j0) + 16 * wsub;
#pragma unroll
        for (int ng = 0; ng < 2; ng++) {
            float* ap = acc + 4 * ng;
            const int col = goff + 8 * ng + 2 * q;
            const int r0 = base_row + p;
            if (r0 < NN)     red_add_v2(out + (size_t)r0 * 32 + col, ap[0], ap[1]);
            if (r0 + 8 < NN) red_add_v2(out + (size_t)(r0 + 8) * 32 + col, ap[2], ap[3]);
        }
#pragma unroll
        for (int a = 0; a < 8; a++) acc[a] = 0.f;
    };

    // ---- prologue: two tiles in flight, group-0 S staged, B in regs ----
    issue_tile(0);
    issue_tile(1);
    stage_S(0);
    __syncthreads();
    load_B();

    for (int m = 0; m < NMAT; m++) {
        cp_wait<1>();      // tile m resident (tile m+1 may still be in flight)
        __syncthreads();   // + all warps finished compute on tile m-1

        if (m + 2 < NMAT) issue_tile(m + 2);

        if (m == 3) {      // group switch: restage S (group-A compute all done)
            stage_S(1);
            __syncthreads();
            load_B();
        }

        const float* __restrict__ Tb = smem + (m - (m / 3) * 3) * BT * TPD;
        const float w = (m < 3) ? wA[m] : wB[m - 3];

        if (side == 0) {
            const float* __restrict__ Ta = Tb + (16 * wsub + p) * TPD + q;
#pragma unroll
            for (int ks = 0; ks < 16; ks++) {
                const int kb = 8 * ks;
                const uint32_t a0 = __float_as_uint(Ta[kb]);           // f32->tf32 by HW truncation
                const uint32_t a1 = __float_as_uint(Ta[8 * TPD + kb]);
                const uint32_t a2 = __float_as_uint(Ta[kb + 4]);
                const uint32_t a3 = __float_as_uint(Ta[8 * TPD + kb + 4]);
                mma_tf32(araw,     a0, a1, a2, a3, breg[4 * ks + 0], breg[4 * ks + 1]);
                mma_tf32(araw + 4, a0, a1, a2, a3, breg[4 * ks + 2], breg[4 * ks + 3]);
            }
        } else {
            const float* __restrict__ Tt = Tb + 16 * wsub + p;
#pragma unroll
            for (int ks = 0; ks < 16; ks++) {
                const int kb = 8 * ks;
                const float* __restrict__ Tc = Tt + (kb + q) * TPD;
                const uint32_t a0 = __float_as_uint(Tc[0]);
                const uint32_t a1 = __float_as_uint(Tc[8]);
                const uint32_t a2 = __float_as_uint(Tc[4 * TPD]);
                const uint32_t a3 = __float_as_uint(Tc[4 * TPD + 8]);
                mma_tf32(araw,     a0, a1, a2, a3, breg[4 * ks + 0], breg[4 * ks + 1]);
                mma_tf32(araw + 4, a0, a1, a2, a3, breg[4 * ks + 2], breg[4 * ks + 3]);
            }
        }

        // fold matrix weight into the running group accumulator
#pragma unroll
        for (int a = 0; a < 8; a++) { acc[a] = fmaf(w, araw[a], acc[a]); araw[a] = 0.f; }

        if (m == 2) flush(0);          // group A -> cols 0..15
        if (m == NMAT - 1) flush(16);  // group B -> cols 16..31
    }
}

extern "C" void kernel_launch(void* const* d_in, const int* in_sizes, int n_in,
                              void* d_out, int out_size) {
    const float* feature = (const float*)d_in[0];  // [5000,128]
    const float* A       = (const float*)d_in[1];  // [3,5000,5000]
    const float* At      = (const float*)d_in[2];  // [9,5000,5000]
    const float* wb2     = (const float*)d_in[3];  // [3,1]
    const float* wb      = (const float*)d_in[4];  // [9,1]
    const float* W3      = (const float*)d_in[5];  // [128,16]
    const float* b3      = (const float*)d_in[6];  // [16]
    const float* W1      = (const float*)d_in[7];  // [128,16]
    const float* b1      = (const float*)d_in[8];  // [16]
    float* out = (float*)d_out;                    // [5000,32]

    fame_prep<<<NN, 128>>>(feature, W3, b3, W1, b1, out);

    const int smem_bytes = (3 * BT * TPD + 2 * 16 * SPD) * (int)sizeof(float);
    cudaFuncSetAttribute(fame_main, cudaFuncAttributeMaxDynamicSharedMemorySize, smem_bytes);
    dim3 grid((NN + BT - 1) / BT, (NN + BT - 1) / BT);
    fame_main<<<grid, NTHREADS, smem_bytes>>>(A, At, wb2, wb, out);
}